// round 3
// baseline (speedup 1.0000x reference)
#include <cuda_runtime.h>
#include <math.h>

// Problem constants
#define B_   2
#define S_   2048
#define D_   1024
#define H_   16
#define HD_  64
#define M_   4096            // B_*S_

// GEMM tiling
#define BM 128
#define BN 128
#define BK 16

// Scratch (device globals: allocation-free per harness rules)
__device__ float g_q[(size_t)M_ * D_];
__device__ float g_k[(size_t)M_ * D_];
__device__ float g_v[(size_t)M_ * D_];
__device__ float g_ctx[(size_t)M_ * D_];

// ---------------------------------------------------------------------------
// Shared 128x128x16 fp32 SIMT GEMM body: C[M_,D_] = A[M_,D_] @ W[D_,D_] + bias
// 256 threads, each owns an 8x8 microtile. N=K=1024 hardcoded.
// ---------------------------------------------------------------------------
__device__ __forceinline__ void gemm_body(
    const float* __restrict__ A, const float* __restrict__ W,
    const float* __restrict__ bias, float* __restrict__ C)
{
    __shared__ float As[BK][BM];   // transposed A tile
    __shared__ float Bs[BK][BN];

    const int tid  = threadIdx.x;
    const int tx   = tid & 15;     // 0..15 (column group)
    const int ty   = tid >> 4;     // 0..15 (row group)
    const int row0 = blockIdx.y * BM;
    const int col0 = blockIdx.x * BN;

    float acc[8][8];
#pragma unroll
    for (int i = 0; i < 8; i++)
#pragma unroll
        for (int j = 0; j < 8; j++) acc[i][j] = 0.0f;

    for (int k0 = 0; k0 < D_; k0 += BK) {
        // Load A tile 128x16 (2048 floats = 512 float4 / 256 threads = 2 each),
        // stored transposed. Load B tile 16x128 likewise.
#pragma unroll
        for (int i = 0; i < 2; i++) {
            int f  = tid + i * 256;
            int r  = f >> 2;               // 0..127
            int c4 = (f & 3) << 2;         // 0,4,8,12
            float4 a = *(const float4*)(A + (size_t)(row0 + r) * D_ + k0 + c4);
            As[c4 + 0][r] = a.x;
            As[c4 + 1][r] = a.y;
            As[c4 + 2][r] = a.z;
            As[c4 + 3][r] = a.w;
            int rb = f >> 5;               // 0..15
            int cb = (f & 31) << 2;        // 0..124
            *(float4*)&Bs[rb][cb] =
                *(const float4*)(W + (size_t)(k0 + rb) * D_ + col0 + cb);
        }
        __syncthreads();

#pragma unroll
        for (int kk = 0; kk < BK; kk++) {
            float af[8], bf[8];
            *(float4*)&af[0] = *(const float4*)&As[kk][ty * 8];
            *(float4*)&af[4] = *(const float4*)&As[kk][ty * 8 + 4];
            *(float4*)&bf[0] = *(const float4*)&Bs[kk][tx * 8];
            *(float4*)&bf[4] = *(const float4*)&Bs[kk][tx * 8 + 4];
#pragma unroll
            for (int i = 0; i < 8; i++)
#pragma unroll
                for (int j = 0; j < 8; j++)
                    acc[i][j] += af[i] * bf[j];
        }
        __syncthreads();
    }

    // Epilogue: + bias, store
#pragma unroll
    for (int i = 0; i < 8; i++) {
        size_t r = (size_t)(row0 + ty * 8 + i);
#pragma unroll
        for (int j = 0; j < 8; j += 4) {
            int c = col0 + tx * 8 + j;
            float4 o;
            o.x = acc[i][j + 0] + bias[c + 0];
            o.y = acc[i][j + 1] + bias[c + 1];
            o.z = acc[i][j + 2] + bias[c + 2];
            o.w = acc[i][j + 3] + bias[c + 3];
            *(float4*)(C + r * D_ + c) = o;
        }
    }
}

// Batched Q/K/V projection: blockIdx.z selects which GEMM (keeps grid at 768
// blocks so the chip stays full instead of 3 underfilled launches).
__global__ void __launch_bounds__(256) qkv_gemm_kernel(
    const float* __restrict__ X,  const float* __restrict__ Ctx,
    const float* __restrict__ Wq, const float* __restrict__ Wk,
    const float* __restrict__ Wv, const float* __restrict__ bq,
    const float* __restrict__ bk, const float* __restrict__ bv,
    float* __restrict__ Q, float* __restrict__ K, float* __restrict__ V)
{
    const int z = blockIdx.z;
    const float* A = (z == 0) ? X  : Ctx;
    const float* W = (z == 0) ? Wq : (z == 1) ? Wk : Wv;
    const float* b = (z == 0) ? bq : (z == 1) ? bk : bv;
    float*       C = (z == 0) ? Q  : (z == 1) ? K  : V;
    gemm_body(A, W, b, C);
}

__global__ void __launch_bounds__(256) out_gemm_kernel(
    const float* __restrict__ A, const float* __restrict__ W,
    const float* __restrict__ bias, float* __restrict__ C)
{
    gemm_body(A, W, bias, C);
}

// ---------------------------------------------------------------------------
// RoPE over the full hidden dim, pre-head-split.
// cos/sin tables are concat(freqs,freqs) => cos[s,d] == cos[s,d+512]; each
// thread rotates one (d, d+512) pair in place. blockIdx.y: 0 -> Q, 1 -> K.
// ---------------------------------------------------------------------------
__global__ void __launch_bounds__(256) rope_kernel(
    float* __restrict__ Q, float* __restrict__ K)
{
    const int idx = blockIdx.x * blockDim.x + threadIdx.x;   // < M_*512
    float* base = blockIdx.y ? K : Q;
    const int row = idx >> 9;          // 0..4095
    const int d   = idx & 511;
    const int s   = row & (S_ - 1);

    // inv_freq[d] = 10000^(-d/512)  (reference: arange(0,1024,2)/1024 = d/512)
    const float invf = exp2f((float)d * (-13.28771237954945f / 512.0f));
    const float ang  = (float)s * invf;
    float sn, cs;
    sincosf(ang, &sn, &cs);

    float* p = base + (size_t)row * D_;
    const float lo = p[d];
    const float hi = p[d + 512];
    p[d]       = lo * cs - hi * sn;
    p[d + 512] = hi * cs + lo * sn;
}

// ---------------------------------------------------------------------------
// Per-position head-mixing attention. One CTA (128 threads) per (b,s):
//   scores[16,16] = q·k^T / 8 ; softmax over heads ; ctx = attn @ v [16,64]
// ctx is scattered directly into the transpose(0,2,1,3).reshape layout:
//   row' = h*128 + s/16 ; col' = (s%16)*64 + d   (64-float contiguous chunks)
// ---------------------------------------------------------------------------
__global__ void __launch_bounds__(128) attn_kernel(
    const float* __restrict__ Q, const float* __restrict__ K,
    const float* __restrict__ V, float* __restrict__ ctx2,
    float* __restrict__ attn_out, int write_attn)
{
    __shared__ float sq[H_][HD_ + 1];   // +1 pad: conflict-free column reads
    __shared__ float sk[H_][HD_ + 1];
    __shared__ float sv[H_][HD_ + 1];
    __shared__ float sc[H_][H_ + 1];

    const int m   = blockIdx.x;         // b*S + s
    const int tid = threadIdx.x;

    const float4* q4 = (const float4*)(Q + (size_t)m * D_);
    const float4* k4 = (const float4*)(K + (size_t)m * D_);
    const float4* v4 = (const float4*)(V + (size_t)m * D_);
#pragma unroll
    for (int i = tid; i < 256; i += 128) {
        const int r = i >> 4;
        const int c = (i & 15) << 2;
        float4 a = q4[i];
        sq[r][c] = a.x; sq[r][c + 1] = a.y; sq[r][c + 2] = a.z; sq[r][c + 3] = a.w;
        float4 b = k4[i];
        sk[r][c] = b.x; sk[r][c + 1] = b.y; sk[r][c + 2] = b.z; sk[r][c + 3] = b.w;
        float4 v = v4[i];
        sv[r][c] = v.x; sv[r][c + 1] = v.y; sv[r][c + 2] = v.z; sv[r][c + 3] = v.w;
    }
    __syncthreads();

    // scores (256 entries / 128 threads)
    for (int e = tid; e < 256; e += 128) {
        const int h = e >> 4, t = e & 15;
        float s = 0.0f;
#pragma unroll
        for (int d = 0; d < HD_; d++) s += sq[h][d] * sk[t][d];
        sc[h][t] = s * 0.125f;          // 1/sqrt(64)
    }
    __syncthreads();

    // softmax over heads (16 rows, one per thread)
    if (tid < H_) {
        float mx = -1e30f;
#pragma unroll
        for (int t = 0; t < H_; t++) mx = fmaxf(mx, sc[tid][t]);
        float ex[H_];
        float sum = 0.0f;
#pragma unroll
        for (int t = 0; t < H_; t++) { ex[t] = expf(sc[tid][t] - mx); sum += ex[t]; }
        const float inv = 1.0f / sum;
#pragma unroll
        for (int t = 0; t < H_; t++) sc[tid][t] = ex[t] * inv;
    }
    __syncthreads();

    if (write_attn) {
        for (int e = tid; e < 256; e += 128)
            attn_out[(size_t)m * 256 + e] = sc[e >> 4][e & 15];
    }

    // ctx = attn @ v, scattered into the reshaped layout
    const int b = m >> 11;              // / S_
    const int s = m & (S_ - 1);
    for (int o = tid; o < 1024; o += 128) {
        const int h = o >> 6, d = o & 63;
        float a = 0.0f;
#pragma unroll
        for (int t = 0; t < H_; t++) a += sc[h][t] * sv[t][d];
        const size_t oi = (size_t)b * (S_ * D_)
                        + (size_t)(h * 128 + (s >> 4)) * D_
                        + ((size_t)(s & 15) << 6) + d;
        ctx2[oi] = a;
    }
}

// ---------------------------------------------------------------------------
extern "C" void kernel_launch(void* const* d_in, const int* in_sizes, int n_in,
                              void* d_out, int out_size)
{
    const float* inputs  = (const float*)d_in[0];
    const float* context = (const float*)d_in[1];
    const float* Wq = (const float*)d_in[2];
    const float* bq = (const float*)d_in[3];
    const float* Wk = (const float*)d_in[4];
    const float* bk = (const float*)d_in[5];
    const float* Wv = (const float*)d_in[6];
    const float* bv = (const float*)d_in[7];
    const float* Wo = (const float*)d_in[8];
    const float* bo = (const float*)d_in[9];
    float* out = (float*)d_out;

    static float *pq = nullptr, *pk = nullptr, *pv = nullptr, *pc = nullptr;
    if (!pq) {
        void* p;
        cudaGetSymbolAddress(&p, g_q);   pq = (float*)p;
        cudaGetSymbolAddress(&p, g_k);   pk = (float*)p;
        cudaGetSymbolAddress(&p, g_v);   pv = (float*)p;
        cudaGetSymbolAddress(&p, g_ctx); pc = (float*)p;
    }

    // 1) Q/K/V projections (batched via grid.z => 768 CTAs, full chip)
    dim3 gq(D_ / BN, M_ / BM, 3);
    qkv_gemm_kernel<<<gq, 256>>>(inputs, context, Wq, Wk, Wv, bq, bk, bv,
                                 pq, pk, pv);

    // 2) RoPE in place on Q and K
    rope_kernel<<<dim3((M_ * 512) / 256, 2), 256>>>(pq, pk);

    // 3) Per-position head attention + reshape scatter (+ attn output)
    const int write_attn = (out_size >= M_ * D_ + M_ * H_ * H_);
    attn_kernel<<<M_, 128>>>(pq, pk, pv, pc, out + (size_t)M_ * D_, write_attn);

    // 4) Output projection
    out_gemm_kernel<<<dim3(D_ / BN, M_ / BM, 1), 256>>>(pc, Wo, bo, out);
}

// round 6
// speedup vs baseline: 2.1855x; 2.1855x over previous
#include <cuda_runtime.h>
#include <cuda_bf16.h>
#include <math.h>

// Problem constants
#define B_   2
#define S_   2048
#define D_   1024
#define H_   16
#define HD_  64
#define M_   4096            // B_*S_

// ---------------------------------------------------------------------------
// Scratch (device globals: allocation-free per harness rules)
// ---------------------------------------------------------------------------
__device__ float g_q[(size_t)M_ * D_];
__device__ float g_k[(size_t)M_ * D_];
__device__ float g_v[(size_t)M_ * D_];
__device__ float g_ctx[(size_t)M_ * D_];

// bf16 hi/lo splits of the three GEMM activations
__device__ __nv_bfloat16 g_xh[(size_t)M_ * D_], g_xl[(size_t)M_ * D_];  // inputs
__device__ __nv_bfloat16 g_ch[(size_t)M_ * D_], g_cl[(size_t)M_ * D_];  // context
__device__ __nv_bfloat16 g_th[(size_t)M_ * D_], g_tl[(size_t)M_ * D_];  // ctx post-attn

// bf16 hi/lo splits of TRANSPOSED weights, [N,K] layout. 0=Wq 1=Wk 2=Wv 3=Wo
__device__ __nv_bfloat16 g_wh[4][(size_t)D_ * D_];
__device__ __nv_bfloat16 g_wl[4][(size_t)D_ * D_];

// ---------------------------------------------------------------------------
// PTX helpers (sm_80-era: compile clean through compute_103)
// ---------------------------------------------------------------------------
__device__ __forceinline__ unsigned smem_u32(const void* p) {
    unsigned a;
    asm("{ .reg .u64 t; cvta.to.shared.u64 t, %1; cvt.u32.u64 %0, t; }"
        : "=r"(a) : "l"(p));
    return a;
}

__device__ __forceinline__ void cp16(unsigned saddr, const void* gaddr) {
    asm volatile(
        "{ .reg .u64 g; cvta.to.global.u64 g, %1;"
        "  cp.async.cg.shared.global [%0], [g], 16; }"
        :: "r"(saddr), "l"(gaddr) : "memory");
}

#define CP_COMMIT()  asm volatile("cp.async.commit_group;" ::: "memory")
#define CP_WAIT(n)   asm volatile("cp.async.wait_group " #n ";" ::: "memory")

#define LDSM4(r, addr)                                                        \
    asm volatile("ldmatrix.sync.aligned.m8n8.x4.shared.b16 {%0,%1,%2,%3},[%4];" \
        : "=r"((r)[0]), "=r"((r)[1]), "=r"((r)[2]), "=r"((r)[3]) : "r"(addr))

#define MMA16816(c, a, b0, b1)                                                \
    asm volatile(                                                             \
        "mma.sync.aligned.m16n8k16.row.col.f32.bf16.bf16.f32 "                \
        "{%0,%1,%2,%3},{%4,%5,%6,%7},{%8,%9},{%0,%1,%2,%3};"                  \
        : "+f"((c)[0]), "+f"((c)[1]), "+f"((c)[2]), "+f"((c)[3])              \
        : "r"((a)[0]), "r"((a)[1]), "r"((a)[2]), "r"((a)[3]),                 \
          "r"(b0), "r"(b1))

// ---------------------------------------------------------------------------
// Split conversions: fp32 -> (hi bf16, lo bf16), lo = rn(a - (float)hi)
// ---------------------------------------------------------------------------
__global__ void __launch_bounds__(256) split_act_kernel(
    const float* __restrict__ src, int which)
{
    const size_t i = ((size_t)blockIdx.x * 256 + threadIdx.x) * 4;
    const float* s = (which == 2) ? g_ctx : src;
    __nv_bfloat16* h = (which == 0) ? g_xh : (which == 1) ? g_ch : g_th;
    __nv_bfloat16* l = (which == 0) ? g_xl : (which == 1) ? g_cl : g_tl;

    float4 a = *(const float4*)(s + i);
    __nv_bfloat16 h0 = __float2bfloat16(a.x);
    __nv_bfloat16 h1 = __float2bfloat16(a.y);
    __nv_bfloat16 h2 = __float2bfloat16(a.z);
    __nv_bfloat16 h3 = __float2bfloat16(a.w);
    __nv_bfloat16 l0 = __float2bfloat16(a.x - __bfloat162float(h0));
    __nv_bfloat16 l1 = __float2bfloat16(a.y - __bfloat162float(h1));
    __nv_bfloat16 l2 = __float2bfloat16(a.z - __bfloat162float(h2));
    __nv_bfloat16 l3 = __float2bfloat16(a.w - __bfloat162float(h3));

    __nv_bfloat162 p;
    p.x = h0; p.y = h1; ((__nv_bfloat162*)(h + i))[0] = p;
    p.x = h2; p.y = h3; ((__nv_bfloat162*)(h + i))[1] = p;
    p.x = l0; p.y = l1; ((__nv_bfloat162*)(l + i))[0] = p;
    p.x = l2; p.y = l3; ((__nv_bfloat162*)(l + i))[1] = p;
}

// Transpose + split weights: Wt[n,k] = split(W[k,n]); z = Wq/Wk/Wv/Wo
__global__ void __launch_bounds__(256) wsplit_kernel(
    const float* __restrict__ Wq, const float* __restrict__ Wk,
    const float* __restrict__ Wv, const float* __restrict__ Wo)
{
    __shared__ float t[32][33];
    const int z = blockIdx.z;
    const float* W = (z == 0) ? Wq : (z == 1) ? Wk : (z == 2) ? Wv : Wo;
    __nv_bfloat16* th = g_wh[z];
    __nv_bfloat16* tl = g_wl[z];

    const int tx = threadIdx.x & 31, ty = threadIdx.x >> 5;
    const int bx = blockIdx.x, by = blockIdx.y;
#pragma unroll
    for (int j = 0; j < 4; j++)
        t[ty + j * 8][tx] = W[(size_t)(by * 32 + ty + j * 8) * D_ + bx * 32 + tx];
    __syncthreads();
#pragma unroll
    for (int j = 0; j < 4; j++) {
        const int n = bx * 32 + ty + j * 8;
        const int k = by * 32 + tx;
        const float a = t[tx][ty + j * 8];
        __nv_bfloat16 h = __float2bfloat16(a);
        th[(size_t)n * D_ + k] = h;
        tl[(size_t)n * D_ + k] = __float2bfloat16(a - __bfloat162float(h));
    }
}

// ---------------------------------------------------------------------------
// Warp-MMA split-bf16 GEMM: C[4096,1024] = (Ah+Al)@(Bh+Bl)^T + bias
// A*: [M,K] row-major; B*: [N,K] row-major (== col-major k x n for mma).
// CTA 128x128, 8 warps (warp tile 32x64), K-chunk 32, double-buffered
// cp.async, ldmatrix fragments, 3 products into shared fp32 accumulators.
// ---------------------------------------------------------------------------
#define KC      32
#define AST     40                       // padded SMEM row stride (bf16 elems)
#define ARR_B   (128 * AST * 2)          // 10240 B per array
#define STAGE_B (4 * ARR_B)              // Ah|Al|Bh|Bl = 40960 B
#define SMEM_DYN (2 * STAGE_B)           // 81920 B

__device__ __forceinline__ void tc_gemm_body(
    const __nv_bfloat16* __restrict__ Ah, const __nv_bfloat16* __restrict__ Al,
    const __nv_bfloat16* __restrict__ Bh, const __nv_bfloat16* __restrict__ Bl,
    const float* __restrict__ bias, float* __restrict__ C)
{
    extern __shared__ char smem[];
    const unsigned sbase = smem_u32(smem);
    const int tid  = threadIdx.x;
    const int wid  = tid >> 5;
    const int lane = tid & 31;
    const int wm   = wid & 3;            // 4 warps along M (32 rows each)
    const int wn   = wid >> 2;           // 2 warps along N (64 cols each)
    const int row0 = blockIdx.y * 128;
    const int col0 = blockIdx.x * 128;

    const __nv_bfloat16* srcs[4] = {
        Ah + (size_t)row0 * D_, Al + (size_t)row0 * D_,
        Bh + (size_t)col0 * D_, Bl + (size_t)col0 * D_ };

    float acc[2][8][4];
#pragma unroll
    for (int i = 0; i < 2; i++)
#pragma unroll
        for (int j = 0; j < 8; j++)
#pragma unroll
            for (int q = 0; q < 4; q++) acc[i][j][q] = 0.0f;

    // per-lane ldmatrix address offsets (bf16 element units)
    const int aoff = (lane & 15) * AST + ((lane >> 4) << 3);
    const int boff = ((lane & 7) + ((lane & 16) >> 1)) * AST
                   + ((lane & 8) ? 8 : 0);

    // ---- stage loader: 4 arrays x 512 16B-granules / 256 threads ----
    auto load_stage = [&](int buf, int k0) {
        const unsigned st = sbase + buf * STAGE_B;
#pragma unroll
        for (int t = 0; t < 4; t++) {
#pragma unroll
            for (int i = 0; i < 2; i++) {
                const int g = tid + i * 256;          // 0..511
                const int r = g >> 2;                 // tile row
                const int c = g & 3;                  // 16B granule
                cp16(st + t * ARR_B + (unsigned)(r * (AST * 2) + c * 16),
                     srcs[t] + (size_t)r * D_ + k0 + c * 8);
            }
        }
    };

    load_stage(0, 0);
    CP_COMMIT();

    for (int ks = 0; ks < 32; ks++) {
        if (ks + 1 < 32) {
            load_stage((ks + 1) & 1, (ks + 1) * KC);
            CP_COMMIT();
            CP_WAIT(1);
        } else {
            CP_WAIT(0);
        }
        __syncthreads();

        const unsigned st = sbase + (ks & 1) * STAGE_B;
#pragma unroll
        for (int kk = 0; kk < KC; kk += 16) {
            unsigned ah[2][4], al[2][4];
            const unsigned ab = st + 2 * (aoff + kk);
            LDSM4(ah[0], ab + 2 * ((wm * 32 + 0)  * AST));
            LDSM4(ah[1], ab + 2 * ((wm * 32 + 16) * AST));
            LDSM4(al[0], ab + ARR_B + 2 * ((wm * 32 + 0)  * AST));
            LDSM4(al[1], ab + ARR_B + 2 * ((wm * 32 + 16) * AST));
#pragma unroll
            for (int nb = 0; nb < 4; nb++) {
                unsigned bh[4], bl[4];
                const unsigned bb = st + 2 * ARR_B + 2 * (boff + kk)
                                  + 2 * ((wn * 64 + nb * 16) * AST);
                LDSM4(bh, bb);
                LDSM4(bl, bb + ARR_B);
#pragma unroll
                for (int ma = 0; ma < 2; ma++) {
                    MMA16816(acc[ma][2 * nb],     ah[ma], bh[0], bh[1]);
                    MMA16816(acc[ma][2 * nb + 1], ah[ma], bh[2], bh[3]);
                    MMA16816(acc[ma][2 * nb],     ah[ma], bl[0], bl[1]);
                    MMA16816(acc[ma][2 * nb + 1], ah[ma], bl[2], bl[3]);
                    MMA16816(acc[ma][2 * nb],     al[ma], bh[0], bh[1]);
                    MMA16816(acc[ma][2 * nb + 1], al[ma], bh[2], bh[3]);
                }
            }
        }
        __syncthreads();
    }

    // ---- epilogue: + bias, direct fp32 stores ----
#pragma unroll
    for (int ma = 0; ma < 2; ma++) {
        const int r0 = row0 + wm * 32 + ma * 16 + (lane >> 2);
#pragma unroll
        for (int na = 0; na < 8; na++) {
            const int col = col0 + wn * 64 + na * 8 + (lane & 3) * 2;
            const float2 b = *(const float2*)(bias + col);
            const float* c = acc[ma][na];
            *(float2*)(C + (size_t)r0 * D_ + col) =
                make_float2(c[0] + b.x, c[1] + b.y);
            *(float2*)(C + (size_t)(r0 + 8) * D_ + col) =
                make_float2(c[2] + b.x, c[3] + b.y);
        }
    }
}

__global__ void __launch_bounds__(256) tc_gemm_qkv_kernel(
    const float* __restrict__ bq, const float* __restrict__ bk,
    const float* __restrict__ bv)
{
    const int z = blockIdx.z;
    const __nv_bfloat16* Ah = z ? g_ch : g_xh;
    const __nv_bfloat16* Al = z ? g_cl : g_xl;
    const float* bias = (z == 0) ? bq : (z == 1) ? bk : bv;
    float* C = (z == 0) ? g_q : (z == 1) ? g_k : g_v;
    tc_gemm_body(Ah, Al, g_wh[z], g_wl[z], bias, C);
}

__global__ void __launch_bounds__(256) tc_gemm_o_kernel(
    const float* __restrict__ bo, float* __restrict__ out)
{
    tc_gemm_body(g_th, g_tl, g_wh[3], g_wl[3], bo, out);
}

// ---------------------------------------------------------------------------
// RoPE over the full hidden dim, pre-head-split (cos[s,d]==cos[s,d+512]).
// ---------------------------------------------------------------------------
__global__ void __launch_bounds__(256) rope_kernel()
{
    const int idx = blockIdx.x * blockDim.x + threadIdx.x;   // < M_*512
    float* base = blockIdx.y ? g_k : g_q;
    const int row = idx >> 9;
    const int d   = idx & 511;
    const int s   = row & (S_ - 1);

    const float invf = exp2f((float)d * (-13.28771237954945f / 512.0f));
    const float ang  = (float)s * invf;
    float sn, cs;
    sincosf(ang, &sn, &cs);

    float* p = base + (size_t)row * D_;
    const float lo = p[d];
    const float hi = p[d + 512];
    p[d]       = lo * cs - hi * sn;
    p[d + 512] = hi * cs + lo * sn;
}

// ---------------------------------------------------------------------------
// Per-position head-mixing attention (16x16 over heads). One CTA per (b,s).
// ctx scattered into transpose(0,2,1,3).reshape layout for the out-GEMM.
// ---------------------------------------------------------------------------
__global__ void __launch_bounds__(128) attn_kernel(
    float* __restrict__ attn_out, int write_attn)
{
    __shared__ float sq[H_][HD_ + 1];
    __shared__ float sk[H_][HD_ + 1];
    __shared__ float sv[H_][HD_ + 1];
    __shared__ float sc[H_][H_ + 1];

    const int m   = blockIdx.x;
    const int tid = threadIdx.x;

    const float4* q4 = (const float4*)(g_q + (size_t)m * D_);
    const float4* k4 = (const float4*)(g_k + (size_t)m * D_);
    const float4* v4 = (const float4*)(g_v + (size_t)m * D_);
#pragma unroll
    for (int i = tid; i < 256; i += 128) {
        const int r = i >> 4;
        const int c = (i & 15) << 2;
        float4 a = q4[i];
        sq[r][c] = a.x; sq[r][c + 1] = a.y; sq[r][c + 2] = a.z; sq[r][c + 3] = a.w;
        float4 b = k4[i];
        sk[r][c] = b.x; sk[r][c + 1] = b.y; sk[r][c + 2] = b.z; sk[r][c + 3] = b.w;
        float4 v = v4[i];
        sv[r][c] = v.x; sv[r][c + 1] = v.y; sv[r][c + 2] = v.z; sv[r][c + 3] = v.w;
    }
    __syncthreads();

    for (int e = tid; e < 256; e += 128) {
        const int h = e >> 4, t = e & 15;
        float s = 0.0f;
#pragma unroll
        for (int d = 0; d < HD_; d++) s += sq[h][d] * sk[t][d];
        sc[h][t] = s * 0.125f;
    }
    __syncthreads();

    if (tid < H_) {
        float mx = -1e30f;
#pragma unroll
        for (int t = 0; t < H_; t++) mx = fmaxf(mx, sc[tid][t]);
        float ex[H_];
        float sum = 0.0f;
#pragma unroll
        for (int t = 0; t < H_; t++) { ex[t] = expf(sc[tid][t] - mx); sum += ex[t]; }
        const float inv = 1.0f / sum;
#pragma unroll
        for (int t = 0; t < H_; t++) sc[tid][t] = ex[t] * inv;
    }
    __syncthreads();

    if (write_attn) {
        for (int e = tid; e < 256; e += 128)
            attn_out[(size_t)m * 256 + e] = sc[e >> 4][e & 15];
    }

    const int b = m >> 11;
    const int s = m & (S_ - 1);
    for (int o = tid; o < 1024; o += 128) {
        const int h = o >> 6, d = o & 63;
        float a = 0.0f;
#pragma unroll
        for (int t = 0; t < H_; t++) a += sc[h][t] * sv[t][d];
        const size_t oi = (size_t)b * (S_ * D_)
                        + (size_t)(h * 128 + (s >> 4)) * D_
                        + ((size_t)(s & 15) << 6) + d;
        g_ctx[oi] = a;
    }
}

// ---------------------------------------------------------------------------
extern "C" void kernel_launch(void* const* d_in, const int* in_sizes, int n_in,
                              void* d_out, int out_size)
{
    const float* inputs  = (const float*)d_in[0];
    const float* context = (const float*)d_in[1];
    const float* Wq = (const float*)d_in[2];
    const float* bq = (const float*)d_in[3];
    const float* Wk = (const float*)d_in[4];
    const float* bk = (const float*)d_in[5];
    const float* Wv = (const float*)d_in[6];
    const float* bv = (const float*)d_in[7];
    const float* Wo = (const float*)d_in[8];
    const float* bo = (const float*)d_in[9];
    float* out = (float*)d_out;

    // Not a stream op; safe on every call (incl. under capture).
    cudaFuncSetAttribute(tc_gemm_qkv_kernel,
                         cudaFuncAttributeMaxDynamicSharedMemorySize, SMEM_DYN);
    cudaFuncSetAttribute(tc_gemm_o_kernel,
                         cudaFuncAttributeMaxDynamicSharedMemorySize, SMEM_DYN);

    // 1) Split activations and weights into bf16 hi/lo
    split_act_kernel<<<(M_ * D_) / 1024, 256>>>(inputs, 0);
    split_act_kernel<<<(M_ * D_) / 1024, 256>>>(context, 1);
    wsplit_kernel<<<dim3(32, 32, 4), 256>>>(Wq, Wk, Wv, Wo);

    // 2) Q/K/V projections on tensor cores (768 CTAs)
    tc_gemm_qkv_kernel<<<dim3(8, 32, 3), 256, SMEM_DYN>>>(bq, bk, bv);

    // 3) RoPE in place on Q and K
    rope_kernel<<<dim3((M_ * 512) / 256, 2), 256>>>();

    // 4) Per-position head attention + reshape scatter (+ attn output)
    const int write_attn = (out_size >= M_ * D_ + M_ * H_ * H_);
    attn_kernel<<<M_, 128>>>(out + (size_t)M_ * D_, write_attn);

    // 5) Split attention context, then output projection on tensor cores
    split_act_kernel<<<(M_ * D_) / 1024, 256>>>(nullptr, 2);
    tc_gemm_o_kernel<<<dim3(8, 32, 1), 256, SMEM_DYN>>>(bo, out);
}

// round 8
// speedup vs baseline: 2.4607x; 1.1259x over previous
#include <cuda_runtime.h>
#include <cuda_bf16.h>
#include <math.h>

// Problem constants
#define B_   2
#define S_   2048
#define D_   1024
#define H_   16
#define HD_  64
#define M_   4096            // B_*S_

// ---------------------------------------------------------------------------
// Scratch (device globals: allocation-free per harness rules)
// ---------------------------------------------------------------------------
__device__ float g_q[(size_t)M_ * D_];
__device__ float g_k[(size_t)M_ * D_];
__device__ float g_v[(size_t)M_ * D_];

// bf16 hi/lo splits of the three GEMM activations
__device__ __nv_bfloat16 g_xh[(size_t)M_ * D_], g_xl[(size_t)M_ * D_];  // inputs
__device__ __nv_bfloat16 g_ch[(size_t)M_ * D_], g_cl[(size_t)M_ * D_];  // context
__device__ __nv_bfloat16 g_th[(size_t)M_ * D_], g_tl[(size_t)M_ * D_];  // ctx post-attn

// bf16 hi/lo splits of TRANSPOSED weights, [N,K] layout. 0=Wq 1=Wk 2=Wv 3=Wo
__device__ __nv_bfloat16 g_wh[4][(size_t)D_ * D_];
__device__ __nv_bfloat16 g_wl[4][(size_t)D_ * D_];

// ---------------------------------------------------------------------------
// PTX helpers (sm_80-era: compile clean through compute_103)
// ---------------------------------------------------------------------------
__device__ __forceinline__ unsigned smem_u32(const void* p) {
    unsigned a;
    asm("{ .reg .u64 t; cvta.to.shared.u64 t, %1; cvt.u32.u64 %0, t; }"
        : "=r"(a) : "l"(p));
    return a;
}

__device__ __forceinline__ void cp16(unsigned saddr, const void* gaddr) {
    asm volatile(
        "{ .reg .u64 g; cvta.to.global.u64 g, %1;"
        "  cp.async.cg.shared.global [%0], [g], 16; }"
        :: "r"(saddr), "l"(gaddr) : "memory");
}

#define CP_COMMIT()  asm volatile("cp.async.commit_group;" ::: "memory")
#define CP_WAIT(n)   asm volatile("cp.async.wait_group " #n ";" ::: "memory")

#define LDSM4(r, addr)                                                        \
    asm volatile("ldmatrix.sync.aligned.m8n8.x4.shared.b16 {%0,%1,%2,%3},[%4];" \
        : "=r"((r)[0]), "=r"((r)[1]), "=r"((r)[2]), "=r"((r)[3]) : "r"(addr))

#define MMA16816(c, a, b0, b1)                                                \
    asm volatile(                                                             \
        "mma.sync.aligned.m16n8k16.row.col.f32.bf16.bf16.f32 "                \
        "{%0,%1,%2,%3},{%4,%5,%6,%7},{%8,%9},{%0,%1,%2,%3};"                  \
        : "+f"((c)[0]), "+f"((c)[1]), "+f"((c)[2]), "+f"((c)[3])              \
        : "r"((a)[0]), "r"((a)[1]), "r"((a)[2]), "r"((a)[3]),                 \
          "r"(b0), "r"(b1))

// ---------------------------------------------------------------------------
// Split conversions: fp32 -> (hi bf16, lo bf16), lo = rn(a - (float)hi)
// which: 0 -> inputs->xh/xl, 1 -> context->ch/cl
// ---------------------------------------------------------------------------
__global__ void __launch_bounds__(256) split_act_kernel(
    const float* __restrict__ src, int which)
{
    const size_t i = ((size_t)blockIdx.x * 256 + threadIdx.x) * 4;
    __nv_bfloat16* h = (which == 0) ? g_xh : g_ch;
    __nv_bfloat16* l = (which == 0) ? g_xl : g_cl;

    float4 a = *(const float4*)(src + i);
    __nv_bfloat16 h0 = __float2bfloat16(a.x);
    __nv_bfloat16 h1 = __float2bfloat16(a.y);
    __nv_bfloat16 h2 = __float2bfloat16(a.z);
    __nv_bfloat16 h3 = __float2bfloat16(a.w);
    __nv_bfloat16 l0 = __float2bfloat16(a.x - __bfloat162float(h0));
    __nv_bfloat16 l1 = __float2bfloat16(a.y - __bfloat162float(h1));
    __nv_bfloat16 l2 = __float2bfloat16(a.z - __bfloat162float(h2));
    __nv_bfloat16 l3 = __float2bfloat16(a.w - __bfloat162float(h3));

    __nv_bfloat162 p;
    p.x = h0; p.y = h1; ((__nv_bfloat162*)(h + i))[0] = p;
    p.x = h2; p.y = h3; ((__nv_bfloat162*)(h + i))[1] = p;
    p.x = l0; p.y = l1; ((__nv_bfloat162*)(l + i))[0] = p;
    p.x = l2; p.y = l3; ((__nv_bfloat162*)(l + i))[1] = p;
}

// Transpose + split weights: Wt[n,k] = split(W[k,n]); z = Wq/Wk/Wv/Wo
__global__ void __launch_bounds__(256) wsplit_kernel(
    const float* __restrict__ Wq, const float* __restrict__ Wk,
    const float* __restrict__ Wv, const float* __restrict__ Wo)
{
    __shared__ float t[32][33];
    const int z = blockIdx.z;
    const float* W = (z == 0) ? Wq : (z == 1) ? Wk : (z == 2) ? Wv : Wo;
    __nv_bfloat16* th = g_wh[z];
    __nv_bfloat16* tl = g_wl[z];

    const int tx = threadIdx.x & 31, ty = threadIdx.x >> 5;
    const int bx = blockIdx.x, by = blockIdx.y;
#pragma unroll
    for (int j = 0; j < 4; j++)
        t[ty + j * 8][tx] = W[(size_t)(by * 32 + ty + j * 8) * D_ + bx * 32 + tx];
    __syncthreads();
#pragma unroll
    for (int j = 0; j < 4; j++) {
        const int n = bx * 32 + ty + j * 8;
        const int k = by * 32 + tx;
        const float a = t[tx][ty + j * 8];
        __nv_bfloat16 h = __float2bfloat16(a);
        th[(size_t)n * D_ + k] = h;
        tl[(size_t)n * D_ + k] = __float2bfloat16(a - __bfloat162float(h));
    }
}

// ---------------------------------------------------------------------------
// Warp-MMA split-bf16 GEMM: C[4096,1024] = (Ah+Al)@(Bh+Bl)^T + bias
// CTA 128x128, 8 warps (warp tile 32x64), K-chunk 16, 4-stage cp.async
// multistage pipeline (one barrier/iter), 3 products (hh,hl,lh) into fp32.
// ---------------------------------------------------------------------------
#define KC      16
#define NSTAGE  4
#define AST     24                        // padded SMEM row stride (bf16 elems)
#define ARR_B   (128 * AST * 2)           // 6144 B per array
#define STAGE_B (4 * ARR_B)               // Ah|Al|Bh|Bl = 24576 B
#define SMEM_DYN (NSTAGE * STAGE_B)       // 98304 B
#define NITER   (D_ / KC)                 // 64

__device__ __forceinline__ void tc_gemm_body(
    const __nv_bfloat16* __restrict__ Ah, const __nv_bfloat16* __restrict__ Al,
    const __nv_bfloat16* __restrict__ Bh, const __nv_bfloat16* __restrict__ Bl,
    const float* __restrict__ bias, float* __restrict__ C)
{
    extern __shared__ char smem[];
    const unsigned sbase = smem_u32(smem);
    const int tid  = threadIdx.x;
    const int wid  = tid >> 5;
    const int lane = tid & 31;
    const int wm   = wid & 3;             // 4 warps along M (32 rows each)
    const int wn   = wid >> 2;            // 2 warps along N (64 cols each)
    const int row0 = blockIdx.y * 128;
    const int col0 = blockIdx.x * 128;

    const __nv_bfloat16* srcs[4] = {
        Ah + (size_t)row0 * D_, Al + (size_t)row0 * D_,
        Bh + (size_t)col0 * D_, Bl + (size_t)col0 * D_ };

    float acc[2][8][4];
#pragma unroll
    for (int i = 0; i < 2; i++)
#pragma unroll
        for (int j = 0; j < 8; j++)
#pragma unroll
            for (int q = 0; q < 4; q++) acc[i][j][q] = 0.0f;

    // per-lane ldmatrix offsets (bf16 element units)
    const int aoff = (lane & 15) * AST + ((lane >> 4) << 3);
    const int boff = ((lane & 7) + ((lane & 16) >> 1)) * AST
                   + ((lane & 8) ? 8 : 0);

    // stage loader: 4 arrays x (128 rows x 2 16B-granules) / 256 thr = 4 cp16
    const int lr = tid >> 1;              // row 0..127
    const int lc = tid & 1;               // granule 0/1
    auto load_stage = [&](int buf, int k0) {
        const unsigned st = sbase + buf * STAGE_B + (unsigned)(lr * (AST * 2) + lc * 16);
        const size_t go = (size_t)lr * D_ + k0 + lc * 8;
#pragma unroll
        for (int t = 0; t < 4; t++)
            cp16(st + t * ARR_B, srcs[t] + go);
    };

#pragma unroll
    for (int p = 0; p < NSTAGE - 1; p++) {
        load_stage(p, p * KC);
        CP_COMMIT();
    }

    for (int ks = 0; ks < NITER; ks++) {
        CP_WAIT(2);                       // stage ks resident
        __syncthreads();

        const unsigned st = sbase + (ks & (NSTAGE - 1)) * STAGE_B;
        unsigned ah[2][4], al[2][4];
        const unsigned ab = st + 2 * aoff;
        LDSM4(ah[0], ab + 2 * ((wm * 32 + 0)  * AST));
        LDSM4(ah[1], ab + 2 * ((wm * 32 + 16) * AST));
        LDSM4(al[0], ab + ARR_B + 2 * ((wm * 32 + 0)  * AST));
        LDSM4(al[1], ab + ARR_B + 2 * ((wm * 32 + 16) * AST));
#pragma unroll
        for (int nb = 0; nb < 4; nb++) {
            unsigned bh[4], bl[4];
            const unsigned bb = st + 2 * ARR_B + 2 * boff
                              + 2 * ((wn * 64 + nb * 16) * AST);
            LDSM4(bh, bb);
            LDSM4(bl, bb + ARR_B);
#pragma unroll
            for (int ma = 0; ma < 2; ma++) {
                MMA16816(acc[ma][2 * nb],     ah[ma], bh[0], bh[1]);
                MMA16816(acc[ma][2 * nb + 1], ah[ma], bh[2], bh[3]);
                MMA16816(acc[ma][2 * nb],     ah[ma], bl[0], bl[1]);
                MMA16816(acc[ma][2 * nb + 1], ah[ma], bl[2], bl[3]);
                MMA16816(acc[ma][2 * nb],     al[ma], bh[0], bh[1]);
                MMA16816(acc[ma][2 * nb + 1], al[ma], bh[2], bh[3]);
            }
        }

        if (ks + NSTAGE - 1 < NITER)
            load_stage((ks + NSTAGE - 1) & (NSTAGE - 1), (ks + NSTAGE - 1) * KC);
        CP_COMMIT();                      // one group per iter (may be empty)
    }

    // ---- epilogue: + bias, direct fp32 stores ----
#pragma unroll
    for (int ma = 0; ma < 2; ma++) {
        const int r0 = row0 + wm * 32 + ma * 16 + (lane >> 2);
#pragma unroll
        for (int na = 0; na < 8; na++) {
            const int col = col0 + wn * 64 + na * 8 + (lane & 3) * 2;
            const float2 b = *(const float2*)(bias + col);
            const float* c = acc[ma][na];
            *(float2*)(C + (size_t)r0 * D_ + col) =
                make_float2(c[0] + b.x, c[1] + b.y);
            *(float2*)(C + (size_t)(r0 + 8) * D_ + col) =
                make_float2(c[2] + b.x, c[3] + b.y);
        }
    }
}

__global__ void __launch_bounds__(256, 2) tc_gemm_qkv_kernel(
    const float* __restrict__ bq, const float* __restrict__ bk,
    const float* __restrict__ bv)
{
    const int z = blockIdx.z;
    const __nv_bfloat16* Ah = z ? g_ch : g_xh;
    const __nv_bfloat16* Al = z ? g_cl : g_xl;
    const float* bias = (z == 0) ? bq : (z == 1) ? bk : bv;
    float* C = (z == 0) ? g_q : (z == 1) ? g_k : g_v;
    tc_gemm_body(Ah, Al, g_wh[z], g_wl[z], bias, C);
}

__global__ void __launch_bounds__(256, 2) tc_gemm_o_kernel(
    const float* __restrict__ bo, float* __restrict__ out)
{
    tc_gemm_body(g_th, g_tl, g_wh[3], g_wl[3], bo, out);
}

// ---------------------------------------------------------------------------
// Fused RoPE + per-position head-mixing attention. One CTA per (b,s).
// RoPE pair (d, d+512) lives at smem rows (r, r+8), same column.
// Epilogue writes bf16 hi/lo split of ctx directly (feeds the out-GEMM),
// scattered into the transpose(0,2,1,3).reshape layout.
// ---------------------------------------------------------------------------
__global__ void __launch_bounds__(128) attn_kernel(
    float* __restrict__ attn_out, int write_attn)
{
    __shared__ float sq[H_][HD_ + 1];
    __shared__ float sk[H_][HD_ + 1];
    __shared__ float sv[H_][HD_ + 1];
    __shared__ float sc[H_][H_ + 1];

    const int m   = blockIdx.x;
    const int tid = threadIdx.x;
    const int s   = m & (S_ - 1);

    const float4* q4 = (const float4*)(g_q + (size_t)m * D_);
    const float4* k4 = (const float4*)(g_k + (size_t)m * D_);
    const float4* v4 = (const float4*)(g_v + (size_t)m * D_);
#pragma unroll
    for (int i = tid; i < 256; i += 128) {
        const int r = i >> 4;
        const int c = (i & 15) << 2;
        float4 a = q4[i];
        sq[r][c] = a.x; sq[r][c + 1] = a.y; sq[r][c + 2] = a.z; sq[r][c + 3] = a.w;
        float4 b = k4[i];
        sk[r][c] = b.x; sk[r][c + 1] = b.y; sk[r][c + 2] = b.z; sk[r][c + 3] = b.w;
        float4 v = v4[i];
        sv[r][c] = v.x; sv[r][c + 1] = v.y; sv[r][c + 2] = v.z; sv[r][c + 3] = v.w;
    }
    __syncthreads();

    // RoPE in SMEM: element d pairs with d+512 -> rows (d>>6, (d>>6)+8), col d&63
#pragma unroll
    for (int e = tid; e < 512; e += 128) {
        const float invf = exp2f((float)e * (-13.28771237954945f / 512.0f));
        float sn, cs;
        sincosf((float)s * invf, &sn, &cs);
        const int r = e >> 6, c = e & 63;

        const float qlo = sq[r][c], qhi = sq[r + 8][c];
        sq[r][c]     = qlo * cs - qhi * sn;
        sq[r + 8][c] = qhi * cs + qlo * sn;

        const float klo = sk[r][c], khi = sk[r + 8][c];
        sk[r][c]     = klo * cs - khi * sn;
        sk[r + 8][c] = khi * cs + klo * sn;
    }
    __syncthreads();

    for (int e = tid; e < 256; e += 128) {
        const int h = e >> 4, t = e & 15;
        float v = 0.0f;
#pragma unroll
        for (int d = 0; d < HD_; d++) v += sq[h][d] * sk[t][d];
        sc[h][t] = v * 0.125f;
    }
    __syncthreads();

    if (tid < H_) {
        float mx = -1e30f;
#pragma unroll
        for (int t = 0; t < H_; t++) mx = fmaxf(mx, sc[tid][t]);
        float ex[H_];
        float sum = 0.0f;
#pragma unroll
        for (int t = 0; t < H_; t++) { ex[t] = expf(sc[tid][t] - mx); sum += ex[t]; }
        const float inv = 1.0f / sum;
#pragma unroll
        for (int t = 0; t < H_; t++) sc[tid][t] = ex[t] * inv;
    }
    __syncthreads();

    if (write_attn) {
        for (int e = tid; e < 256; e += 128)
            attn_out[(size_t)m * 256 + e] = sc[e >> 4][e & 15];
    }

    // ctx = attn @ v, split to bf16 hi/lo, scattered into reshaped layout
    const int b = m >> 11;
    for (int o = tid; o < 1024; o += 128) {
        const int h = o >> 6, d = o & 63;
        float a = 0.0f;
#pragma unroll
        for (int t = 0; t < H_; t++) a += sc[h][t] * sv[t][d];
        const size_t oi = (size_t)b * (S_ * D_)
                        + (size_t)(h * 128 + (s >> 4)) * D_
                        + ((size_t)(s & 15) << 6) + d;
        const __nv_bfloat16 hh = __float2bfloat16(a);
        g_th[oi] = hh;
        g_tl[oi] = __float2bfloat16(a - __bfloat162float(hh));
    }
}

// ---------------------------------------------------------------------------
extern "C" void kernel_launch(void* const* d_in, const int* in_sizes, int n_in,
                              void* d_out, int out_size)
{
    const float* inputs  = (const float*)d_in[0];
    const float* context = (const float*)d_in[1];
    const float* Wq = (const float*)d_in[2];
    const float* bq = (const float*)d_in[3];
    const float* Wk = (const float*)d_in[4];
    const float* bk = (const float*)d_in[5];
    const float* Wv = (const float*)d_in[6];
    const float* bv = (const float*)d_in[7];
    const float* Wo = (const float*)d_in[8];
    const float* bo = (const float*)d_in[9];
    float* out = (float*)d_out;

    cudaFuncSetAttribute(tc_gemm_qkv_kernel,
                         cudaFuncAttributeMaxDynamicSharedMemorySize, SMEM_DYN);
    cudaFuncSetAttribute(tc_gemm_o_kernel,
                         cudaFuncAttributeMaxDynamicSharedMemorySize, SMEM_DYN);

    // 1) Split activations and weights into bf16 hi/lo
    split_act_kernel<<<(M_ * D_) / 1024, 256>>>(inputs, 0);
    split_act_kernel<<<(M_ * D_) / 1024, 256>>>(context, 1);
    wsplit_kernel<<<dim3(32, 32, 4), 256>>>(Wq, Wk, Wv, Wo);

    // 2) Q/K/V projections on tensor cores (768 CTAs)
    tc_gemm_qkv_kernel<<<dim3(8, 32, 3), 256, SMEM_DYN>>>(bq, bk, bv);

    // 3) Fused RoPE + head attention + bf16-split reshape scatter
    const int write_attn = (out_size >= M_ * D_ + M_ * H_ * H_);
    attn_kernel<<<M_, 128>>>(out + (size_t)M_ * D_, write_attn);

    // 4) Output projection on tensor cores
    tc_gemm_o_kernel<<<dim3(8, 32, 1), 256, SMEM_DYN>>>(bo, out);
}